// round 10
// baseline (speedup 1.0000x reference)
#include <cuda_runtime.h>
#include <cuda_fp16.h>
#include <cstdint>

#define NN 100000      // nodes
#define DD 64          // feature dim
#define EE 1250000     // edges
#define ND (NN * DD)
#define NH2 (ND / 4)   // uint2 count for fp16 feature arrays (4 halfs per uint2)
#define WMAX 64        // ELL width; P(Poisson(12.5) >= 64) ~ 1e-23

// ---------------- scratch (device globals, allocation-free) ----------------
__device__ int   g_cnt0[NN];
__device__ int   g_cnt1[NN];
__device__ float g_degf[NN];
__device__ float g_dis[NN];
__device__ int2  g_ell0[(size_t)NN * WMAX];  // edge graph: {col, w} -> {col, w_norm} after L1
__device__ int2  g_ell1[(size_t)NN * WMAX];  // nb graph:   {col, w}
__device__ uint2 g_xh[NH2];      // x fp16
__device__ uint2 g_lxh[NH2];     // Lx fp16
__device__ uint2 g_outh[NH2];    // out fp16
__device__ uint2 g_b1h[NH2];     // N(out) fp16
__device__ uint2 g_b2h[NH2];     // N(out[shuf]) fp16

// ---------------- helpers ----------------
__device__ __forceinline__ void fma4(float* acc, uint2 v, float w) {
    __half2 h0 = *reinterpret_cast<__half2*>(&v.x);
    __half2 h1 = *reinterpret_cast<__half2*>(&v.y);
    float2 f0 = __half22float2(h0);
    float2 f1 = __half22float2(h1);
    acc[0] += w * f0.x;
    acc[1] += w * f0.y;
    acc[2] += w * f1.x;
    acc[3] += w * f1.y;
}

__device__ __forceinline__ float4 unpack4(uint2 v) {
    __half2 h0 = *reinterpret_cast<__half2*>(&v.x);
    __half2 h1 = *reinterpret_cast<__half2*>(&v.y);
    float2 f0 = __half22float2(h0);
    float2 f1 = __half22float2(h1);
    return make_float4(f0.x, f0.y, f1.x, f1.y);
}

__device__ __forceinline__ uint2 pack4(float a, float b, float c, float d) {
    uint2 u;
    __half2 h0 = __floats2half2_rn(a, b);
    __half2 h1 = __floats2half2_rn(c, d);
    u.x = *reinterpret_cast<unsigned*>(&h0);
    u.y = *reinterpret_cast<unsigned*>(&h1);
    return u;
}

// merge the two half-warp partial sums (lanes xor 16)
__device__ __forceinline__ void reduce16(float* acc, int n) {
#pragma unroll
    for (int k = 0; k < 8; k++) {
        if (k < n) acc[k] += __shfl_xor_sync(0xffffffffu, acc[k], 16);
    }
}

// ---------------- build: fused ELL append (both graphs) + fp16 x ----------------
__global__ void append_all_kernel(const int* __restrict__ er, const int* __restrict__ ec,
                                  const float* __restrict__ ew,
                                  const int* __restrict__ nr, const int* __restrict__ nc,
                                  const float* __restrict__ nw,
                                  const float* __restrict__ x) {
    int i = blockIdx.x * blockDim.x + threadIdx.x;
    if (i < EE) {
        int r = er[i];
        float w = ew[i];
        atomicAdd(&g_degf[r], w);
        int p = atomicAdd(&g_cnt0[r], 1);
        g_ell0[(size_t)r * WMAX + p] = make_int2(ec[i], __float_as_int(w));
    } else if (i < 2 * EE) {
        int k = i - EE;
        int r = nr[k];
        int p = atomicAdd(&g_cnt1[r], 1);
        g_ell1[(size_t)r * WMAX + p] = make_int2(nc[k], __float_as_int(nw[k]));
    } else if (i < 2 * EE + NH2) {
        int k = i - 2 * EE;
        float4 v = *(const float4*)(x + (size_t)k * 4);
        g_xh[k] = pack4(v.x, v.y, v.z, v.w);
    }
}

__global__ void dis_kernel() {
    int i = blockIdx.x * blockDim.x + threadIdx.x;
    if (i < NN) {
        float d = g_degf[i];
        g_dis[i] = (d > 0.f) ? rsqrtf(d) : 0.f;
    }
}

// ---------------- SPMM kernels: 32 lanes per row ----------------
// Half-warp h processes edges j = h, h+2, h+4, ... ; features: 16 sublanes x 4.

// Lx = x - Anorm x; normalizes weights in-place and writes lxh fp16
__global__ void spmm_L1_kernel(const float* __restrict__ x) {
    int t = blockIdx.x * blockDim.x + threadIdx.x;
    int r = t >> 5;
    if (r >= NN) return;
    unsigned lane = t & 31;
    unsigned half = lane >> 4;
    unsigned sub  = lane & 15;
    int deg = g_cnt0[r];
    float dr = g_dis[r];
    const size_t base = (size_t)r * WMAX;
    float acc[4] = {0.f, 0.f, 0.f, 0.f};
    int j = (int)half;
    for (; j + 2 < deg; j += 4) {
        int2 e0 = g_ell0[base + j];
        int2 e1 = g_ell0[base + j + 2];
        float d0 = __ldg(&g_dis[e0.x]);
        float d1 = __ldg(&g_dis[e1.x]);
        uint2 v0 = g_xh[(unsigned)e0.x * 16u + sub];
        uint2 v1 = g_xh[(unsigned)e1.x * 16u + sub];
        float w0 = dr * __int_as_float(e0.y) * d0;
        float w1 = dr * __int_as_float(e1.y) * d1;
        if (sub == 0) {
            g_ell0[base + j].y     = __float_as_int(w0);
            g_ell0[base + j + 2].y = __float_as_int(w1);
        }
        fma4(acc, v0, w0);
        fma4(acc, v1, w1);
    }
    if (j < deg) {
        int2 e0 = g_ell0[base + j];
        float w0 = dr * __int_as_float(e0.y) * __ldg(&g_dis[e0.x]);
        if (sub == 0) g_ell0[base + j].y = __float_as_int(w0);
        uint2 v0 = g_xh[(unsigned)e0.x * 16u + sub];
        fma4(acc, v0, w0);
    }
    reduce16(acc, 4);
    if (half == 0) {
        float4 xv = *(const float4*)(x + (size_t)r * DD + sub * 4u);
        g_lxh[(unsigned)r * 16u + sub] =
            pack4(xv.x - acc[0], xv.y - acc[1], xv.z - acc[2], xv.w - acc[3]);
    }
}

// out = c0*x + c1*Lx + c2*(Lx - Anorm*Lx); writes out fp32 + outh fp16
__global__ void spmm_L2_kernel(const float* __restrict__ x,
                               const float* __restrict__ temp,
                               float* __restrict__ out) {
    int t = blockIdx.x * blockDim.x + threadIdx.x;
    int r = t >> 5;
    if (r >= NN) return;
    unsigned lane = t & 31;
    unsigned half = lane >> 4;
    unsigned sub  = lane & 15;
    int deg = g_cnt0[r];
    const size_t base = (size_t)r * WMAX;
    float acc[4] = {0.f, 0.f, 0.f, 0.f};
    int j = (int)half;
    for (; j + 2 < deg; j += 4) {
        int2 e0 = g_ell0[base + j];
        int2 e1 = g_ell0[base + j + 2];
        uint2 v0 = g_lxh[(unsigned)e0.x * 16u + sub];
        uint2 v1 = g_lxh[(unsigned)e1.x * 16u + sub];
        fma4(acc, v0, __int_as_float(e0.y));
        fma4(acc, v1, __int_as_float(e1.y));
    }
    if (j < deg) {
        int2 e0 = g_ell0[base + j];
        uint2 v0 = g_lxh[(unsigned)e0.x * 16u + sub];
        fma4(acc, v0, __int_as_float(e0.y));
    }
    reduce16(acc, 4);
    if (half == 0) {
        float t0 = fmaxf(__ldg(temp + 0), 0.f);
        float t1 = fmaxf(__ldg(temp + 1), 0.f);
        float t2 = fmaxf(__ldg(temp + 2), 0.f);
        float c0 = t0;
        float c1 = t1 - t0;
        float c2 = (t0 + t2 - 2.f * t1) * 0.25f;
        float4 xv = *(const float4*)(x + (size_t)r * DD + sub * 4u);
        float4 lv = unpack4(g_lxh[(unsigned)r * 16u + sub]);
        float o0 = c0 * xv.x + c1 * lv.x + c2 * (lv.x - acc[0]);
        float o1 = c0 * xv.y + c1 * lv.y + c2 * (lv.y - acc[1]);
        float o2 = c0 * xv.z + c1 * lv.z + c2 * (lv.z - acc[2]);
        float o3 = c0 * xv.w + c1 * lv.w + c2 * (lv.w - acc[3]);
        *(float4*)(out + (size_t)r * DD + sub * 4u) = make_float4(o0, o1, o2, o3);
        g_outh[(unsigned)r * 16u + sub] = pack4(o0, o1, o2, o3);
    }
}

// dual hop 1: b1h[r] = sum w*outh[col]; b2h[r] = sum w*outh[shuf[col]]
__global__ void spmm_N1_kernel(const int* __restrict__ shuf) {
    int t = blockIdx.x * blockDim.x + threadIdx.x;
    int r = t >> 5;
    if (r >= NN) return;
    unsigned lane = t & 31;
    unsigned half = lane >> 4;
    unsigned sub  = lane & 15;
    int deg = g_cnt1[r];
    const size_t base = (size_t)r * WMAX;
    float acc[8] = {0.f, 0.f, 0.f, 0.f, 0.f, 0.f, 0.f, 0.f};  // [0:4)=pos, [4:8)=neg
    int j = (int)half;
    for (; j + 2 < deg; j += 4) {
        int2 e0 = g_ell1[base + j];
        int2 e1 = g_ell1[base + j + 2];
        int s0 = __ldg(shuf + e0.x);
        int s1 = __ldg(shuf + e1.x);
        uint2 vp0 = g_outh[(unsigned)e0.x * 16u + sub];
        uint2 vp1 = g_outh[(unsigned)e1.x * 16u + sub];
        uint2 vn0 = g_outh[(unsigned)s0 * 16u + sub];
        uint2 vn1 = g_outh[(unsigned)s1 * 16u + sub];
        float w0 = __int_as_float(e0.y), w1 = __int_as_float(e1.y);
        fma4(acc,     vp0, w0);
        fma4(acc,     vp1, w1);
        fma4(acc + 4, vn0, w0);
        fma4(acc + 4, vn1, w1);
    }
    if (j < deg) {
        int2 e0 = g_ell1[base + j];
        int s0 = __ldg(shuf + e0.x);
        float w0 = __int_as_float(e0.y);
        uint2 vp0 = g_outh[(unsigned)e0.x * 16u + sub];
        uint2 vn0 = g_outh[(unsigned)s0 * 16u + sub];
        fma4(acc,     vp0, w0);
        fma4(acc + 4, vn0, w0);
    }
    reduce16(acc, 8);
    if (half == 0) {
        g_b1h[(unsigned)r * 16u + sub] = pack4(acc[0], acc[1], acc[2], acc[3]);
        g_b2h[(unsigned)r * 16u + sub] = pack4(acc[4], acc[5], acc[6], acc[7]);
    }
}

// dual hop 2: zp[r] = sum w*b1h[col]; zn[r] = sum w*b2h[col] (fp32 out)
__global__ void spmm_N2_kernel(float* __restrict__ zp, float* __restrict__ zn) {
    int t = blockIdx.x * blockDim.x + threadIdx.x;
    int r = t >> 5;
    if (r >= NN) return;
    unsigned lane = t & 31;
    unsigned half = lane >> 4;
    unsigned sub  = lane & 15;
    int deg = g_cnt1[r];
    const size_t base = (size_t)r * WMAX;
    float acc[8] = {0.f, 0.f, 0.f, 0.f, 0.f, 0.f, 0.f, 0.f};
    int j = (int)half;
    for (; j + 2 < deg; j += 4) {
        int2 e0 = g_ell1[base + j];
        int2 e1 = g_ell1[base + j + 2];
        uint2 vp0 = g_b1h[(unsigned)e0.x * 16u + sub];
        uint2 vn0 = g_b2h[(unsigned)e0.x * 16u + sub];
        uint2 vp1 = g_b1h[(unsigned)e1.x * 16u + sub];
        uint2 vn1 = g_b2h[(unsigned)e1.x * 16u + sub];
        float w0 = __int_as_float(e0.y), w1 = __int_as_float(e1.y);
        fma4(acc,     vp0, w0);
        fma4(acc + 4, vn0, w0);
        fma4(acc,     vp1, w1);
        fma4(acc + 4, vn1, w1);
    }
    if (j < deg) {
        int2 e0 = g_ell1[base + j];
        float w0 = __int_as_float(e0.y);
        uint2 vp0 = g_b1h[(unsigned)e0.x * 16u + sub];
        uint2 vn0 = g_b2h[(unsigned)e0.x * 16u + sub];
        fma4(acc,     vp0, w0);
        fma4(acc + 4, vn0, w0);
    }
    reduce16(acc, 8);
    if (half == 0) {
        *(float4*)(zp + (size_t)r * DD + sub * 4u) = make_float4(acc[0], acc[1], acc[2], acc[3]);
        *(float4*)(zn + (size_t)r * DD + sub * 4u) = make_float4(acc[4], acc[5], acc[6], acc[7]);
    }
}

extern "C" void kernel_launch(void* const* d_in, const int* in_sizes, int n_in,
                              void* d_out, int out_size) {
    const float* x    = (const float*)d_in[0];
    const int*   shuf = (const int*)  d_in[1];
    const int*   ei   = (const int*)  d_in[2];
    const float* ew   = (const float*)d_in[3];
    const int*   ni   = (const int*)  d_in[4];
    const float* nw   = (const float*)d_in[5];
    const float* temp = (const float*)d_in[6];
    float* out = (float*)d_out;   // [out | z_pos | z_neg]

    const int* erow = ei;
    const int* ecol = ei + EE;
    const int* nrow = ni;
    const int* ncol = ni + EE;

    void *p_cnt0, *p_cnt1, *p_degf;
    cudaGetSymbolAddress(&p_cnt0, g_cnt0);
    cudaGetSymbolAddress(&p_cnt1, g_cnt1);
    cudaGetSymbolAddress(&p_degf, g_degf);

    const int TB = 256;
    const int blkN   = (NN + TB - 1) / TB;
    const int blkALL = (2 * EE + NH2 + TB - 1) / TB;
    const int blkR32 = (NN * 32 + TB - 1) / TB;

    // ---- build: zero counters, fused append (both graphs) + fp16 x, dis ----
    cudaMemsetAsync(p_cnt0, 0, NN * sizeof(int), 0);
    cudaMemsetAsync(p_cnt1, 0, NN * sizeof(int), 0);
    cudaMemsetAsync(p_degf, 0, NN * sizeof(float), 0);
    append_all_kernel<<<blkALL, TB>>>(erow, ecol, ew, nrow, ncol, nw, x);
    dis_kernel<<<blkN, TB>>>();

    // ---- spectral polynomial ----
    spmm_L1_kernel<<<blkR32, TB>>>(x);
    spmm_L2_kernel<<<blkR32, TB>>>(x, temp, out);

    // ---- z_pos / z_neg ----
    spmm_N1_kernel<<<blkR32, TB>>>(shuf);
    spmm_N2_kernel<<<blkR32, TB>>>(out + (size_t)ND, out + 2 * (size_t)ND);
}

// round 11
// speedup vs baseline: 1.0964x; 1.0964x over previous
#include <cuda_runtime.h>
#include <cuda_fp16.h>
#include <cstdint>

#define NN 100000      // nodes
#define DD 64          // feature dim
#define EE 1250000     // edges
#define ND (NN * DD)
#define NH2 (ND / 4)   // uint2 count for fp16 feature arrays (4 halfs per uint2)
#define WMAX 64        // ELL width; P(Poisson(12.5) >= 64) ~ 1e-23

// ---------------- scratch (device globals, allocation-free) ----------------
// g_meta: [0:NN)=cnt0, [NN:2NN)=cnt1, [2NN:3NN)=degf (float bits) — one memset
__device__ int   g_meta[3 * NN];
__device__ int2  g_ell0[(size_t)NN * WMAX];  // edge graph: {col, w} -> {col, w_norm} after L1
__device__ int2  g_ell1[(size_t)NN * WMAX];  // nb graph:   {col, w}
__device__ uint2 g_xh[NH2];      // x fp16
__device__ uint2 g_lxh[NH2];     // Lx fp16
__device__ uint2 g_outh[NH2];    // out fp16
__device__ uint2 g_b1h[NH2];     // N(out) fp16
__device__ uint2 g_b2h[NH2];     // N(out[shuf]) fp16

// ---------------- helpers ----------------
__device__ __forceinline__ void fma4(float* acc, uint2 v, float w) {
    __half2 h0 = *reinterpret_cast<__half2*>(&v.x);
    __half2 h1 = *reinterpret_cast<__half2*>(&v.y);
    float2 f0 = __half22float2(h0);
    float2 f1 = __half22float2(h1);
    acc[0] += w * f0.x;
    acc[1] += w * f0.y;
    acc[2] += w * f1.x;
    acc[3] += w * f1.y;
}

__device__ __forceinline__ float4 unpack4(uint2 v) {
    __half2 h0 = *reinterpret_cast<__half2*>(&v.x);
    __half2 h1 = *reinterpret_cast<__half2*>(&v.y);
    float2 f0 = __half22float2(h0);
    float2 f1 = __half22float2(h1);
    return make_float4(f0.x, f0.y, f1.x, f1.y);
}

__device__ __forceinline__ uint2 pack4(float a, float b, float c, float d) {
    uint2 u;
    __half2 h0 = __floats2half2_rn(a, b);
    __half2 h1 = __floats2half2_rn(c, d);
    u.x = *reinterpret_cast<unsigned*>(&h0);
    u.y = *reinterpret_cast<unsigned*>(&h1);
    return u;
}

__device__ __forceinline__ float inv_sqrt_deg(int bits) {
    float d = __int_as_float(bits);
    return (d > 0.f) ? rsqrtf(d) : 0.f;
}

// ---------------- build: fused ELL append (both graphs) + fp16 x ----------------
__global__ void append_all_kernel(const int* __restrict__ er, const int* __restrict__ ec,
                                  const float* __restrict__ ew,
                                  const int* __restrict__ nr, const int* __restrict__ nc,
                                  const float* __restrict__ nw,
                                  const float* __restrict__ x) {
    int i = blockIdx.x * blockDim.x + threadIdx.x;
    if (i < EE) {
        int r = er[i];
        float w = ew[i];
        atomicAdd((float*)&g_meta[2 * NN + r], w);
        int p = atomicAdd(&g_meta[r], 1);
        g_ell0[(size_t)r * WMAX + p] = make_int2(ec[i], __float_as_int(w));
    } else if (i < 2 * EE) {
        int k = i - EE;
        int r = nr[k];
        int p = atomicAdd(&g_meta[NN + r], 1);
        g_ell1[(size_t)r * WMAX + p] = make_int2(nc[k], __float_as_int(nw[k]));
    } else if (i < 2 * EE + NH2) {
        int k = i - 2 * EE;
        float4 v = *(const float4*)(x + (size_t)k * 4);
        g_xh[k] = pack4(v.x, v.y, v.z, v.w);
    }
}

// ---------------- SPMM kernels: 16 lanes per row, 4 features per lane ----------------

// Lx = x - Anorm x; computes dis inline, normalizes weights in-place, writes lxh fp16
__global__ void spmm_L1_kernel() {
    int t = blockIdx.x * blockDim.x + threadIdx.x;
    int r = t >> 4;
    if (r >= NN) return;
    unsigned lane = t & 15;
    int deg = g_meta[r];
    float dr = inv_sqrt_deg(__ldg(&g_meta[2 * NN + r]));
    const size_t base = (size_t)r * WMAX;
    float acc[4] = {0.f, 0.f, 0.f, 0.f};
    int j = 0;
    for (; j + 2 <= deg; j += 2) {
        int2 e0 = g_ell0[base + j], e1 = g_ell0[base + j + 1];
        float d0 = inv_sqrt_deg(__ldg(&g_meta[2 * NN + e0.x]));
        float d1 = inv_sqrt_deg(__ldg(&g_meta[2 * NN + e1.x]));
        uint2 v0 = g_xh[(unsigned)e0.x * 16u + lane];
        uint2 v1 = g_xh[(unsigned)e1.x * 16u + lane];
        float w0 = dr * __int_as_float(e0.y) * d0;
        float w1 = dr * __int_as_float(e1.y) * d1;
        if (lane == 0) {
            g_ell0[base + j].y     = __float_as_int(w0);
            g_ell0[base + j + 1].y = __float_as_int(w1);
        }
        fma4(acc, v0, w0);
        fma4(acc, v1, w1);
    }
    if (j < deg) {
        int2 e0 = g_ell0[base + j];
        float w0 = dr * __int_as_float(e0.y) * inv_sqrt_deg(__ldg(&g_meta[2 * NN + e0.x]));
        if (lane == 0) g_ell0[base + j].y = __float_as_int(w0);
        uint2 v0 = g_xh[(unsigned)e0.x * 16u + lane];
        fma4(acc, v0, w0);
    }
    float4 xv = unpack4(g_xh[(unsigned)r * 16u + lane]);
    g_lxh[(unsigned)r * 16u + lane] =
        pack4(xv.x - acc[0], xv.y - acc[1], xv.z - acc[2], xv.w - acc[3]);
}

// out = c0*x + c1*Lx + c2*(Lx - Anorm*Lx); writes out fp32 + outh fp16
__global__ void spmm_L2_kernel(const float* __restrict__ temp,
                               float* __restrict__ out) {
    int t = blockIdx.x * blockDim.x + threadIdx.x;
    int r = t >> 4;
    if (r >= NN) return;
    unsigned lane = t & 15;
    int deg = g_meta[r];
    const size_t base = (size_t)r * WMAX;
    float acc[4] = {0.f, 0.f, 0.f, 0.f};
    int j = 0;
    for (; j + 2 <= deg; j += 2) {
        int2 e0 = g_ell0[base + j], e1 = g_ell0[base + j + 1];
        uint2 v0 = g_lxh[(unsigned)e0.x * 16u + lane];
        uint2 v1 = g_lxh[(unsigned)e1.x * 16u + lane];
        fma4(acc, v0, __int_as_float(e0.y));
        fma4(acc, v1, __int_as_float(e1.y));
    }
    if (j < deg) {
        int2 e0 = g_ell0[base + j];
        uint2 v0 = g_lxh[(unsigned)e0.x * 16u + lane];
        fma4(acc, v0, __int_as_float(e0.y));
    }
    float t0 = fmaxf(__ldg(temp + 0), 0.f);
    float t1 = fmaxf(__ldg(temp + 1), 0.f);
    float t2 = fmaxf(__ldg(temp + 2), 0.f);
    float c0 = t0;
    float c1 = t1 - t0;
    float c2 = (t0 + t2 - 2.f * t1) * 0.25f;
    float4 xv = unpack4(g_xh[(unsigned)r * 16u + lane]);
    float4 lv = unpack4(g_lxh[(unsigned)r * 16u + lane]);
    float o0 = c0 * xv.x + c1 * lv.x + c2 * (lv.x - acc[0]);
    float o1 = c0 * xv.y + c1 * lv.y + c2 * (lv.y - acc[1]);
    float o2 = c0 * xv.z + c1 * lv.z + c2 * (lv.z - acc[2]);
    float o3 = c0 * xv.w + c1 * lv.w + c2 * (lv.w - acc[3]);
    *(float4*)(out + (size_t)r * DD + lane * 4u) = make_float4(o0, o1, o2, o3);
    g_outh[(unsigned)r * 16u + lane] = pack4(o0, o1, o2, o3);
}

// dual hop 1: b1h[r] = sum w*outh[col]; b2h[r] = sum w*outh[shuf[col]]
__global__ void spmm_N1_kernel(const int* __restrict__ shuf) {
    int t = blockIdx.x * blockDim.x + threadIdx.x;
    int r = t >> 4;
    if (r >= NN) return;
    unsigned lane = t & 15;
    int deg = g_meta[NN + r];
    const size_t base = (size_t)r * WMAX;
    float ap[4] = {0.f, 0.f, 0.f, 0.f};
    float an[4] = {0.f, 0.f, 0.f, 0.f};
    int j = 0;
    for (; j + 2 <= deg; j += 2) {
        int2 e0 = g_ell1[base + j], e1 = g_ell1[base + j + 1];
        int s0 = __ldg(shuf + e0.x);
        int s1 = __ldg(shuf + e1.x);
        float w0 = __int_as_float(e0.y), w1 = __int_as_float(e1.y);
        uint2 vp0 = g_outh[(unsigned)e0.x * 16u + lane];
        uint2 vp1 = g_outh[(unsigned)e1.x * 16u + lane];
        uint2 vn0 = g_outh[(unsigned)s0 * 16u + lane];
        uint2 vn1 = g_outh[(unsigned)s1 * 16u + lane];
        fma4(ap, vp0, w0);
        fma4(ap, vp1, w1);
        fma4(an, vn0, w0);
        fma4(an, vn1, w1);
    }
    if (j < deg) {
        int2 e0 = g_ell1[base + j];
        int s0 = __ldg(shuf + e0.x);
        float w0 = __int_as_float(e0.y);
        uint2 vp0 = g_outh[(unsigned)e0.x * 16u + lane];
        uint2 vn0 = g_outh[(unsigned)s0 * 16u + lane];
        fma4(ap, vp0, w0);
        fma4(an, vn0, w0);
    }
    g_b1h[(unsigned)r * 16u + lane] = pack4(ap[0], ap[1], ap[2], ap[3]);
    g_b2h[(unsigned)r * 16u + lane] = pack4(an[0], an[1], an[2], an[3]);
}

// dual hop 2: zp[r] = sum w*b1h[col]; zn[r] = sum w*b2h[col] (fp32 out)
__global__ void spmm_N2_kernel(float* __restrict__ zp, float* __restrict__ zn) {
    int t = blockIdx.x * blockDim.x + threadIdx.x;
    int r = t >> 4;
    if (r >= NN) return;
    unsigned lane = t & 15;
    int deg = g_meta[NN + r];
    const size_t base = (size_t)r * WMAX;
    float ap[4] = {0.f, 0.f, 0.f, 0.f};
    float an[4] = {0.f, 0.f, 0.f, 0.f};
    int j = 0;
    for (; j + 2 <= deg; j += 2) {
        int2 e0 = g_ell1[base + j], e1 = g_ell1[base + j + 1];
        float w0 = __int_as_float(e0.y), w1 = __int_as_float(e1.y);
        uint2 vp0 = g_b1h[(unsigned)e0.x * 16u + lane];
        uint2 vn0 = g_b2h[(unsigned)e0.x * 16u + lane];
        uint2 vp1 = g_b1h[(unsigned)e1.x * 16u + lane];
        uint2 vn1 = g_b2h[(unsigned)e1.x * 16u + lane];
        fma4(ap, vp0, w0);
        fma4(an, vn0, w0);
        fma4(ap, vp1, w1);
        fma4(an, vn1, w1);
    }
    if (j < deg) {
        int2 e0 = g_ell1[base + j];
        float w0 = __int_as_float(e0.y);
        uint2 vp0 = g_b1h[(unsigned)e0.x * 16u + lane];
        uint2 vn0 = g_b2h[(unsigned)e0.x * 16u + lane];
        fma4(ap, vp0, w0);
        fma4(an, vn0, w0);
    }
    *(float4*)(zp + (size_t)r * DD + lane * 4u) = make_float4(ap[0], ap[1], ap[2], ap[3]);
    *(float4*)(zn + (size_t)r * DD + lane * 4u) = make_float4(an[0], an[1], an[2], an[3]);
}

extern "C" void kernel_launch(void* const* d_in, const int* in_sizes, int n_in,
                              void* d_out, int out_size) {
    const float* x    = (const float*)d_in[0];
    const int*   shuf = (const int*)  d_in[1];
    const int*   ei   = (const int*)  d_in[2];
    const float* ew   = (const float*)d_in[3];
    const int*   ni   = (const int*)  d_in[4];
    const float* nw   = (const float*)d_in[5];
    const float* temp = (const float*)d_in[6];
    float* out = (float*)d_out;   // [out | z_pos | z_neg]

    const int* erow = ei;
    const int* ecol = ei + EE;
    const int* nrow = ni;
    const int* ncol = ni + EE;

    void* p_meta;
    cudaGetSymbolAddress(&p_meta, g_meta);

    const int TB = 256;
    const int blkALL = (2 * EE + NH2 + TB - 1) / TB;
    const int blkR16 = (NN * 16 + TB - 1) / TB;

    // ---- build: one memset, fused append (both graphs) + fp16 x ----
    cudaMemsetAsync(p_meta, 0, 3 * NN * sizeof(int), 0);
    append_all_kernel<<<blkALL, TB>>>(erow, ecol, ew, nrow, ncol, nw, x);

    // ---- spectral polynomial ----
    spmm_L1_kernel<<<blkR16, TB>>>();
    spmm_L2_kernel<<<blkR16, TB>>>(temp, out);

    // ---- z_pos / z_neg ----
    spmm_N1_kernel<<<blkR16, TB>>>(shuf);
    spmm_N2_kernel<<<blkR16, TB>>>(out + (size_t)ND, out + 2 * (size_t)ND);
}

// round 12
// speedup vs baseline: 1.1185x; 1.0202x over previous
#include <cuda_runtime.h>
#include <cuda_fp16.h>
#include <cstdint>

#define NN 100000      // nodes
#define DD 64          // feature dim
#define EE 1250000     // edges
#define ND (NN * DD)
#define NH2 (ND / 4)   // uint2 count for fp16 feature arrays (4 halfs per uint2)
#define WMAX 64        // ELL width; P(Poisson(12.5) >= 64) ~ 1e-23

// ---------------- scratch (device globals, allocation-free) ----------------
// g_meta: [0:NN)=cnt0, [NN:2NN)=cnt1, [2NN:3NN)=degf (float bits) — one memset
__device__ int   g_meta[3 * NN];
__device__ float g_dis[NN];
__device__ int2  g_ell0[(size_t)NN * WMAX];  // edge graph: {col*16, w_raw}
__device__ int4  g_ell1[(size_t)NN * WMAX];  // nb graph: {col*16, shuf[col]*16, w, 0}
__device__ uint2 g_xh[NH2];      // x fp16
__device__ uint2 g_xs[NH2];      // dis*x fp16 (gather operand for L1)
__device__ uint2 g_lxh[NH2];     // Lx fp16 (row terms)
__device__ uint2 g_lxs[NH2];     // dis*Lx fp16 (gather operand for L2)
__device__ uint2 g_outh[NH2];    // out fp16
__device__ uint2 g_b1h[NH2];     // N(out) fp16
__device__ uint2 g_b2h[NH2];     // N(out[shuf]) fp16

// ---------------- helpers ----------------
__device__ __forceinline__ void fma4(float* acc, uint2 v, float w) {
    __half2 h0 = *reinterpret_cast<__half2*>(&v.x);
    __half2 h1 = *reinterpret_cast<__half2*>(&v.y);
    float2 f0 = __half22float2(h0);
    float2 f1 = __half22float2(h1);
    acc[0] += w * f0.x;
    acc[1] += w * f0.y;
    acc[2] += w * f1.x;
    acc[3] += w * f1.y;
}

__device__ __forceinline__ float4 unpack4(uint2 v) {
    __half2 h0 = *reinterpret_cast<__half2*>(&v.x);
    __half2 h1 = *reinterpret_cast<__half2*>(&v.y);
    float2 f0 = __half22float2(h0);
    float2 f1 = __half22float2(h1);
    return make_float4(f0.x, f0.y, f1.x, f1.y);
}

__device__ __forceinline__ uint2 pack4(float a, float b, float c, float d) {
    uint2 u;
    __half2 h0 = __floats2half2_rn(a, b);
    __half2 h1 = __floats2half2_rn(c, d);
    u.x = *reinterpret_cast<unsigned*>(&h0);
    u.y = *reinterpret_cast<unsigned*>(&h1);
    return u;
}

// ---------------- build: fused ELL append (both graphs) + fp16 x ----------------
__global__ void append_all_kernel(const int* __restrict__ er, const int* __restrict__ ec,
                                  const float* __restrict__ ew,
                                  const int* __restrict__ nr, const int* __restrict__ nc,
                                  const float* __restrict__ nw,
                                  const int* __restrict__ shuf,
                                  const float* __restrict__ x) {
    int i = blockIdx.x * blockDim.x + threadIdx.x;
    if (i < EE) {
        int r = er[i];
        float w = ew[i];
        atomicAdd((float*)&g_meta[2 * NN + r], w);
        int p = atomicAdd(&g_meta[r], 1);
        g_ell0[(size_t)r * WMAX + p] = make_int2(ec[i] * 16, __float_as_int(w));
    } else if (i < 2 * EE) {
        int k = i - EE;
        int r = nr[k];
        int c = nc[k];
        int s = __ldg(shuf + c);
        int p = atomicAdd(&g_meta[NN + r], 1);
        g_ell1[(size_t)r * WMAX + p] = make_int4(c * 16, s * 16, __float_as_int(nw[k]), 0);
    } else if (i < 2 * EE + NH2) {
        int k = i - 2 * EE;
        float4 v = *(const float4*)(x + (size_t)k * 4);
        g_xh[k] = pack4(v.x, v.y, v.z, v.w);
    }
}

// dis[r] = rsqrt(degf[r]) (once per row, shfl-broadcast); xs = dis * x (HMUL2)
__global__ void dis_scale_kernel() {
    int t = blockIdx.x * blockDim.x + threadIdx.x;
    int r = t >> 4;
    if (r >= NN) return;
    unsigned wl = threadIdx.x & 31;
    float dr_l = 0.f;
    if ((wl & 15) == 0) {
        float d = __int_as_float(g_meta[2 * NN + r]);
        dr_l = (d > 0.f) ? rsqrtf(d) : 0.f;
    }
    float dr = __shfl_sync(0xffffffffu, dr_l, wl & 16);
    if ((wl & 15) == 0) g_dis[r] = dr;
    unsigned idx = (unsigned)r * 16u + (t & 15);
    uint2 v = g_xh[idx];
    __half2 dh = __float2half2_rn(dr);
    __half2 a = __hmul2(*reinterpret_cast<__half2*>(&v.x), dh);
    __half2 b = __hmul2(*reinterpret_cast<__half2*>(&v.y), dh);
    uint2 o;
    o.x = *reinterpret_cast<unsigned*>(&a);
    o.y = *reinterpret_cast<unsigned*>(&b);
    g_xs[idx] = o;
}

// ---------------- SPMM kernels: 16 lanes per row, 4 features per lane ----------------

// Lx = x - dis[r] * sum w*xs[col]; writes lxh + lxs fp16
__global__ void spmm_L1_kernel() {
    int t = blockIdx.x * blockDim.x + threadIdx.x;
    int r = t >> 4;
    if (r >= NN) return;
    unsigned lane = t & 15;
    int deg = g_meta[r];
    float dr = g_dis[r];
    const size_t base = (size_t)r * WMAX;
    float acc[4] = {0.f, 0.f, 0.f, 0.f};
    int j = 0;
    for (; j + 2 <= deg; j += 2) {
        int4 ee = *(const int4*)&g_ell0[base + j];   // two edges in one LDG.128
        uint2 v0 = g_xs[(unsigned)ee.x + lane];
        uint2 v1 = g_xs[(unsigned)ee.z + lane];
        fma4(acc, v0, __int_as_float(ee.y));
        fma4(acc, v1, __int_as_float(ee.w));
    }
    if (j < deg) {
        int2 e0 = g_ell0[base + j];
        uint2 v0 = g_xs[(unsigned)e0.x + lane];
        fma4(acc, v0, __int_as_float(e0.y));
    }
    unsigned idx = (unsigned)r * 16u + lane;
    float4 xv = unpack4(g_xh[idx]);
    float l0 = xv.x - dr * acc[0];
    float l1 = xv.y - dr * acc[1];
    float l2 = xv.z - dr * acc[2];
    float l3 = xv.w - dr * acc[3];
    g_lxh[idx] = pack4(l0, l1, l2, l3);
    g_lxs[idx] = pack4(dr * l0, dr * l1, dr * l2, dr * l3);
}

// out = c0*x + c1*Lx + c2*(Lx - dis[r]*sum w*lxs[col]); writes out fp32 + outh fp16
__global__ void spmm_L2_kernel(const float* __restrict__ temp,
                               float* __restrict__ out) {
    int t = blockIdx.x * blockDim.x + threadIdx.x;
    int r = t >> 4;
    if (r >= NN) return;
    unsigned lane = t & 15;
    int deg = g_meta[r];
    float dr = g_dis[r];
    const size_t base = (size_t)r * WMAX;
    float acc[4] = {0.f, 0.f, 0.f, 0.f};
    int j = 0;
    for (; j + 2 <= deg; j += 2) {
        int4 ee = *(const int4*)&g_ell0[base + j];
        uint2 v0 = g_lxs[(unsigned)ee.x + lane];
        uint2 v1 = g_lxs[(unsigned)ee.z + lane];
        fma4(acc, v0, __int_as_float(ee.y));
        fma4(acc, v1, __int_as_float(ee.w));
    }
    if (j < deg) {
        int2 e0 = g_ell0[base + j];
        uint2 v0 = g_lxs[(unsigned)e0.x + lane];
        fma4(acc, v0, __int_as_float(e0.y));
    }
    float t0 = fmaxf(__ldg(temp + 0), 0.f);
    float t1 = fmaxf(__ldg(temp + 1), 0.f);
    float t2 = fmaxf(__ldg(temp + 2), 0.f);
    float c0 = t0;
    float c1 = t1 - t0;
    float c2 = (t0 + t2 - 2.f * t1) * 0.25f;
    unsigned idx = (unsigned)r * 16u + lane;
    float4 xv = unpack4(g_xh[idx]);
    float4 lv = unpack4(g_lxh[idx]);
    float o0 = c0 * xv.x + c1 * lv.x + c2 * (lv.x - dr * acc[0]);
    float o1 = c0 * xv.y + c1 * lv.y + c2 * (lv.y - dr * acc[1]);
    float o2 = c0 * xv.z + c1 * lv.z + c2 * (lv.z - dr * acc[2]);
    float o3 = c0 * xv.w + c1 * lv.w + c2 * (lv.w - dr * acc[3]);
    *(float4*)(out + (size_t)r * DD + lane * 4u) = make_float4(o0, o1, o2, o3);
    g_outh[idx] = pack4(o0, o1, o2, o3);
}

// dual hop 1: b1h[r] = sum w*outh[col]; b2h[r] = sum w*outh[shufcol] (precomputed)
__global__ void spmm_N1_kernel() {
    int t = blockIdx.x * blockDim.x + threadIdx.x;
    int r = t >> 4;
    if (r >= NN) return;
    unsigned lane = t & 15;
    int deg = g_meta[NN + r];
    const size_t base = (size_t)r * WMAX;
    float ap[4] = {0.f, 0.f, 0.f, 0.f};
    float an[4] = {0.f, 0.f, 0.f, 0.f};
    int j = 0;
    for (; j + 2 <= deg; j += 2) {
        int4 e0 = g_ell1[base + j];
        int4 e1 = g_ell1[base + j + 1];
        uint2 vp0 = g_outh[(unsigned)e0.x + lane];
        uint2 vn0 = g_outh[(unsigned)e0.y + lane];
        uint2 vp1 = g_outh[(unsigned)e1.x + lane];
        uint2 vn1 = g_outh[(unsigned)e1.y + lane];
        float w0 = __int_as_float(e0.z), w1 = __int_as_float(e1.z);
        fma4(ap, vp0, w0);
        fma4(an, vn0, w0);
        fma4(ap, vp1, w1);
        fma4(an, vn1, w1);
    }
    if (j < deg) {
        int4 e0 = g_ell1[base + j];
        float w0 = __int_as_float(e0.z);
        uint2 vp0 = g_outh[(unsigned)e0.x + lane];
        uint2 vn0 = g_outh[(unsigned)e0.y + lane];
        fma4(ap, vp0, w0);
        fma4(an, vn0, w0);
    }
    unsigned idx = (unsigned)r * 16u + lane;
    g_b1h[idx] = pack4(ap[0], ap[1], ap[2], ap[3]);
    g_b2h[idx] = pack4(an[0], an[1], an[2], an[3]);
}

// dual hop 2: zp[r] = sum w*b1h[col]; zn[r] = sum w*b2h[col] (fp32 out)
__global__ void spmm_N2_kernel(float* __restrict__ zp, float* __restrict__ zn) {
    int t = blockIdx.x * blockDim.x + threadIdx.x;
    int r = t >> 4;
    if (r >= NN) return;
    unsigned lane = t & 15;
    int deg = g_meta[NN + r];
    const size_t base = (size_t)r * WMAX;
    float ap[4] = {0.f, 0.f, 0.f, 0.f};
    float an[4] = {0.f, 0.f, 0.f, 0.f};
    int j = 0;
    for (; j + 2 <= deg; j += 2) {
        int4 e0 = g_ell1[base + j];
        int4 e1 = g_ell1[base + j + 1];
        uint2 vp0 = g_b1h[(unsigned)e0.x + lane];
        uint2 vn0 = g_b2h[(unsigned)e0.x + lane];
        uint2 vp1 = g_b1h[(unsigned)e1.x + lane];
        uint2 vn1 = g_b2h[(unsigned)e1.x + lane];
        float w0 = __int_as_float(e0.z), w1 = __int_as_float(e1.z);
        fma4(ap, vp0, w0);
        fma4(an, vn0, w0);
        fma4(ap, vp1, w1);
        fma4(an, vn1, w1);
    }
    if (j < deg) {
        int4 e0 = g_ell1[base + j];
        float w0 = __int_as_float(e0.z);
        uint2 vp0 = g_b1h[(unsigned)e0.x + lane];
        uint2 vn0 = g_b2h[(unsigned)e0.x + lane];
        fma4(ap, vp0, w0);
        fma4(an, vn0, w0);
    }
    *(float4*)(zp + (size_t)r * DD + lane * 4u) = make_float4(ap[0], ap[1], ap[2], ap[3]);
    *(float4*)(zn + (size_t)r * DD + lane * 4u) = make_float4(an[0], an[1], an[2], an[3]);
}

extern "C" void kernel_launch(void* const* d_in, const int* in_sizes, int n_in,
                              void* d_out, int out_size) {
    const float* x    = (const float*)d_in[0];
    const int*   shuf = (const int*)  d_in[1];
    const int*   ei   = (const int*)  d_in[2];
    const float* ew   = (const float*)d_in[3];
    const int*   ni   = (const int*)  d_in[4];
    const float* nw   = (const float*)d_in[5];
    const float* temp = (const float*)d_in[6];
    float* out = (float*)d_out;   // [out | z_pos | z_neg]

    const int* erow = ei;
    const int* ecol = ei + EE;
    const int* nrow = ni;
    const int* ncol = ni + EE;

    void* p_meta;
    cudaGetSymbolAddress(&p_meta, g_meta);

    const int TB = 256;
    const int blkALL = (2 * EE + NH2 + TB - 1) / TB;
    const int blkR16 = (NN * 16 + TB - 1) / TB;

    // ---- build: one memset, fused append (both graphs + shuf precompute) + fp16 x ----
    cudaMemsetAsync(p_meta, 0, 3 * NN * sizeof(int), 0);
    append_all_kernel<<<blkALL, TB>>>(erow, ecol, ew, nrow, ncol, nw, shuf, x);
    dis_scale_kernel<<<blkR16, TB>>>();

    // ---- spectral polynomial ----
    spmm_L1_kernel<<<blkR16, TB>>>();
    spmm_L2_kernel<<<blkR16, TB>>>(temp, out);

    // ---- z_pos / z_neg ----
    spmm_N1_kernel<<<blkR16, TB>>>();
    spmm_N2_kernel<<<blkR16, TB>>>(out + (size_t)ND, out + 2 * (size_t)ND);
}

// round 13
// speedup vs baseline: 1.1192x; 1.0006x over previous
#include <cuda_runtime.h>
#include <cuda_fp16.h>
#include <cstdint>

#define NN 100000      // nodes
#define DD 64          // feature dim
#define EE 1250000     // edges
#define ND (NN * DD)
#define NH2 (ND / 4)   // uint2 count for fp16 feature arrays (4 halfs per uint2)
#define WMAX 64        // ELL width; P(Poisson(12.5) >= 64) ~ 1e-23

// ---------------- scratch (device globals, allocation-free) ----------------
// g_meta: [0:NN)=cnt0, [NN:2NN)=cnt1, [2NN:3NN)=degf (float bits) — one memset
__device__ int   g_meta[3 * NN];
__device__ float g_dis[NN];
__device__ int2  g_ell0[(size_t)NN * WMAX];   // edge graph: {col*16, w_raw}
__device__ int2  g_ell1a[(size_t)NN * WMAX];  // nb graph: {col*16, w}
__device__ int   g_ell1s[(size_t)NN * WMAX];  // nb graph: shuf[col]*16
__device__ uint2 g_xh[NH2];      // x fp16
__device__ uint2 g_xs[NH2];      // dis*x fp16 (gather operand for L1)
__device__ uint2 g_lxh[NH2];     // Lx fp16 (row terms)
__device__ uint2 g_lxs[NH2];     // dis*Lx fp16 (gather operand for L2)
__device__ uint2 g_outh[NH2];    // out fp16
__device__ uint4 g_b12[(size_t)NN * 16];  // interleaved {N(out) 8B, N(out[shuf]) 8B} per lane

// ---------------- helpers ----------------
__device__ __forceinline__ void fma4(float* acc, uint2 v, float w) {
    __half2 h0 = *reinterpret_cast<__half2*>(&v.x);
    __half2 h1 = *reinterpret_cast<__half2*>(&v.y);
    float2 f0 = __half22float2(h0);
    float2 f1 = __half22float2(h1);
    acc[0] += w * f0.x;
    acc[1] += w * f0.y;
    acc[2] += w * f1.x;
    acc[3] += w * f1.y;
}

__device__ __forceinline__ float4 unpack4(uint2 v) {
    __half2 h0 = *reinterpret_cast<__half2*>(&v.x);
    __half2 h1 = *reinterpret_cast<__half2*>(&v.y);
    float2 f0 = __half22float2(h0);
    float2 f1 = __half22float2(h1);
    return make_float4(f0.x, f0.y, f1.x, f1.y);
}

__device__ __forceinline__ uint2 pack4(float a, float b, float c, float d) {
    uint2 u;
    __half2 h0 = __floats2half2_rn(a, b);
    __half2 h1 = __floats2half2_rn(c, d);
    u.x = *reinterpret_cast<unsigned*>(&h0);
    u.y = *reinterpret_cast<unsigned*>(&h1);
    return u;
}

// ---------------- build: fused ELL append (both graphs) + fp16 x ----------------
__global__ void append_all_kernel(const int* __restrict__ er, const int* __restrict__ ec,
                                  const float* __restrict__ ew,
                                  const int* __restrict__ nr, const int* __restrict__ nc,
                                  const float* __restrict__ nw,
                                  const int* __restrict__ shuf,
                                  const float* __restrict__ x) {
    int i = blockIdx.x * blockDim.x + threadIdx.x;
    if (i < EE) {
        int r = er[i];
        float w = ew[i];
        atomicAdd((float*)&g_meta[2 * NN + r], w);
        int p = atomicAdd(&g_meta[r], 1);
        g_ell0[(size_t)r * WMAX + p] = make_int2(ec[i] * 16, __float_as_int(w));
    } else if (i < 2 * EE) {
        int k = i - EE;
        int r = nr[k];
        int c = nc[k];
        int s = __ldg(shuf + c);
        int p = atomicAdd(&g_meta[NN + r], 1);
        size_t q = (size_t)r * WMAX + p;
        g_ell1a[q] = make_int2(c * 16, __float_as_int(nw[k]));
        g_ell1s[q] = s * 16;
    } else if (i < 2 * EE + NH2) {
        int k = i - 2 * EE;
        float4 v = *(const float4*)(x + (size_t)k * 4);
        g_xh[k] = pack4(v.x, v.y, v.z, v.w);
    }
}

// dis[r] = rsqrt(degf[r]) (once per row); xs = dis * x (HMUL2)
__global__ void dis_scale_kernel() {
    int t = blockIdx.x * blockDim.x + threadIdx.x;
    int r = t >> 4;
    if (r >= NN) return;
    unsigned wl = threadIdx.x & 31;
    float dr_l = 0.f;
    if ((wl & 15) == 0) {
        float d = __int_as_float(g_meta[2 * NN + r]);
        dr_l = (d > 0.f) ? rsqrtf(d) : 0.f;
    }
    float dr = __shfl_sync(0xffffffffu, dr_l, wl & 16);
    if ((wl & 15) == 0) g_dis[r] = dr;
    unsigned idx = (unsigned)r * 16u + (t & 15);
    uint2 v = g_xh[idx];
    __half2 dh = __float2half2_rn(dr);
    __half2 a = __hmul2(*reinterpret_cast<__half2*>(&v.x), dh);
    __half2 b = __hmul2(*reinterpret_cast<__half2*>(&v.y), dh);
    uint2 o;
    o.x = *reinterpret_cast<unsigned*>(&a);
    o.y = *reinterpret_cast<unsigned*>(&b);
    g_xs[idx] = o;
}

// ---------------- SPMM kernels: 16 lanes per row, 4 features per lane ----------------

// Lx = x - dis[r] * sum w*xs[col]; writes lxh + lxs fp16
__global__ void spmm_L1_kernel() {
    int t = blockIdx.x * blockDim.x + threadIdx.x;
    int r = t >> 4;
    if (r >= NN) return;
    unsigned lane = t & 15;
    int deg = g_meta[r];
    float dr = g_dis[r];
    const size_t base = (size_t)r * WMAX;
    float acc[4] = {0.f, 0.f, 0.f, 0.f};
    int j = 0;
    for (; j + 2 <= deg; j += 2) {
        int4 ee = *(const int4*)&g_ell0[base + j];   // two edges in one LDG.128
        uint2 v0 = g_xs[(unsigned)ee.x + lane];
        uint2 v1 = g_xs[(unsigned)ee.z + lane];
        fma4(acc, v0, __int_as_float(ee.y));
        fma4(acc, v1, __int_as_float(ee.w));
    }
    if (j < deg) {
        int2 e0 = g_ell0[base + j];
        uint2 v0 = g_xs[(unsigned)e0.x + lane];
        fma4(acc, v0, __int_as_float(e0.y));
    }
    unsigned idx = (unsigned)r * 16u + lane;
    float4 xv = unpack4(g_xh[idx]);
    float l0 = xv.x - dr * acc[0];
    float l1 = xv.y - dr * acc[1];
    float l2 = xv.z - dr * acc[2];
    float l3 = xv.w - dr * acc[3];
    g_lxh[idx] = pack4(l0, l1, l2, l3);
    g_lxs[idx] = pack4(dr * l0, dr * l1, dr * l2, dr * l3);
}

// out = c0*x + c1*Lx + c2*(Lx - dis[r]*sum w*lxs[col]); writes out fp32 + outh fp16
__global__ void spmm_L2_kernel(const float* __restrict__ temp,
                               float* __restrict__ out) {
    int t = blockIdx.x * blockDim.x + threadIdx.x;
    int r = t >> 4;
    if (r >= NN) return;
    unsigned lane = t & 15;
    int deg = g_meta[r];
    float dr = g_dis[r];
    const size_t base = (size_t)r * WMAX;
    float acc[4] = {0.f, 0.f, 0.f, 0.f};
    int j = 0;
    for (; j + 2 <= deg; j += 2) {
        int4 ee = *(const int4*)&g_ell0[base + j];
        uint2 v0 = g_lxs[(unsigned)ee.x + lane];
        uint2 v1 = g_lxs[(unsigned)ee.z + lane];
        fma4(acc, v0, __int_as_float(ee.y));
        fma4(acc, v1, __int_as_float(ee.w));
    }
    if (j < deg) {
        int2 e0 = g_ell0[base + j];
        uint2 v0 = g_lxs[(unsigned)e0.x + lane];
        fma4(acc, v0, __int_as_float(e0.y));
    }
    float t0 = fmaxf(__ldg(temp + 0), 0.f);
    float t1 = fmaxf(__ldg(temp + 1), 0.f);
    float t2 = fmaxf(__ldg(temp + 2), 0.f);
    float c0 = t0;
    float c1 = t1 - t0;
    float c2 = (t0 + t2 - 2.f * t1) * 0.25f;
    unsigned idx = (unsigned)r * 16u + lane;
    float4 xv = unpack4(g_xh[idx]);
    float4 lv = unpack4(g_lxh[idx]);
    float o0 = c0 * xv.x + c1 * lv.x + c2 * (lv.x - dr * acc[0]);
    float o1 = c0 * xv.y + c1 * lv.y + c2 * (lv.y - dr * acc[1]);
    float o2 = c0 * xv.z + c1 * lv.z + c2 * (lv.z - dr * acc[2]);
    float o3 = c0 * xv.w + c1 * lv.w + c2 * (lv.w - dr * acc[3]);
    *(float4*)(out + (size_t)r * DD + lane * 4u) = make_float4(o0, o1, o2, o3);
    g_outh[idx] = pack4(o0, o1, o2, o3);
}

// dual hop 1: b12[r] = { sum w*outh[col], sum w*outh[scol] } interleaved per lane
__global__ void spmm_N1_kernel() {
    int t = blockIdx.x * blockDim.x + threadIdx.x;
    int r = t >> 4;
    if (r >= NN) return;
    unsigned lane = t & 15;
    int deg = g_meta[NN + r];
    const size_t base = (size_t)r * WMAX;
    float ap[4] = {0.f, 0.f, 0.f, 0.f};
    float an[4] = {0.f, 0.f, 0.f, 0.f};
    int j = 0;
    for (; j + 2 <= deg; j += 2) {
        int4 ee = *(const int4*)&g_ell1a[base + j];  // {c0,w0,c1,w1}
        int2 ss = *(const int2*)&g_ell1s[base + j];  // {s0,s1}
        uint2 vp0 = g_outh[(unsigned)ee.x + lane];
        uint2 vn0 = g_outh[(unsigned)ss.x + lane];
        uint2 vp1 = g_outh[(unsigned)ee.z + lane];
        uint2 vn1 = g_outh[(unsigned)ss.y + lane];
        float w0 = __int_as_float(ee.y), w1 = __int_as_float(ee.w);
        fma4(ap, vp0, w0);
        fma4(an, vn0, w0);
        fma4(ap, vp1, w1);
        fma4(an, vn1, w1);
    }
    if (j < deg) {
        int2 e0 = g_ell1a[base + j];
        int s0 = g_ell1s[base + j];
        float w0 = __int_as_float(e0.y);
        uint2 vp0 = g_outh[(unsigned)e0.x + lane];
        uint2 vn0 = g_outh[(unsigned)s0 + lane];
        fma4(ap, vp0, w0);
        fma4(an, vn0, w0);
    }
    uint2 up = pack4(ap[0], ap[1], ap[2], ap[3]);
    uint2 un = pack4(an[0], an[1], an[2], an[3]);
    g_b12[(unsigned)r * 16u + lane] = make_uint4(up.x, up.y, un.x, un.y);
}

// dual hop 2: one uint4 gather per edge-lane fetches both pos & neg operands
__global__ void spmm_N2_kernel(float* __restrict__ zp, float* __restrict__ zn) {
    int t = blockIdx.x * blockDim.x + threadIdx.x;
    int r = t >> 4;
    if (r >= NN) return;
    unsigned lane = t & 15;
    int deg = g_meta[NN + r];
    const size_t base = (size_t)r * WMAX;
    float ap[4] = {0.f, 0.f, 0.f, 0.f};
    float an[4] = {0.f, 0.f, 0.f, 0.f};
    int j = 0;
    for (; j + 2 <= deg; j += 2) {
        int4 ee = *(const int4*)&g_ell1a[base + j];
        uint4 v0 = g_b12[(unsigned)ee.x + lane];
        uint4 v1 = g_b12[(unsigned)ee.z + lane];
        float w0 = __int_as_float(ee.y), w1 = __int_as_float(ee.w);
        fma4(ap, make_uint2(v0.x, v0.y), w0);
        fma4(an, make_uint2(v0.z, v0.w), w0);
        fma4(ap, make_uint2(v1.x, v1.y), w1);
        fma4(an, make_uint2(v1.z, v1.w), w1);
    }
    if (j < deg) {
        int2 e0 = g_ell1a[base + j];
        float w0 = __int_as_float(e0.y);
        uint4 v0 = g_b12[(unsigned)e0.x + lane];
        fma4(ap, make_uint2(v0.x, v0.y), w0);
        fma4(an, make_uint2(v0.z, v0.w), w0);
    }
    *(float4*)(zp + (size_t)r * DD + lane * 4u) = make_float4(ap[0], ap[1], ap[2], ap[3]);
    *(float4*)(zn + (size_t)r * DD + lane * 4u) = make_float4(an[0], an[1], an[2], an[3]);
}

extern "C" void kernel_launch(void* const* d_in, const int* in_sizes, int n_in,
                              void* d_out, int out_size) {
    const float* x    = (const float*)d_in[0];
    const int*   shuf = (const int*)  d_in[1];
    const int*   ei   = (const int*)  d_in[2];
    const float* ew   = (const float*)d_in[3];
    const int*   ni   = (const int*)  d_in[4];
    const float* nw   = (const float*)d_in[5];
    const float* temp = (const float*)d_in[6];
    float* out = (float*)d_out;   // [out | z_pos | z_neg]

    const int* erow = ei;
    const int* ecol = ei + EE;
    const int* nrow = ni;
    const int* ncol = ni + EE;

    void* p_meta;
    cudaGetSymbolAddress(&p_meta, g_meta);

    const int TB = 256;
    const int blkALL = (2 * EE + NH2 + TB - 1) / TB;
    const int blkR16 = (NN * 16 + TB - 1) / TB;

    // ---- build: one memset, fused append (both graphs + shuf precompute) + fp16 x ----
    cudaMemsetAsync(p_meta, 0, 3 * NN * sizeof(int), 0);
    append_all_kernel<<<blkALL, TB>>>(erow, ecol, ew, nrow, ncol, nw, shuf, x);
    dis_scale_kernel<<<blkR16, TB>>>();

    // ---- spectral polynomial ----
    spmm_L1_kernel<<<blkR16, TB>>>();
    spmm_L2_kernel<<<blkR16, TB>>>(temp, out);

    // ---- z_pos / z_neg ----
    spmm_N1_kernel<<<blkR16, TB>>>();
    spmm_N2_kernel<<<blkR16, TB>>>(out + (size_t)ND, out + 2 * (size_t)ND);
}

// round 14
// speedup vs baseline: 1.2014x; 1.0734x over previous
#include <cuda_runtime.h>
#include <cuda_fp16.h>
#include <cstdint>

#define NN 100000      // nodes
#define DD 64          // feature dim
#define EE 1250000     // edges
#define ND (NN * DD)
#define NH2 (ND / 4)   // uint2 count for fp16 feature arrays (4 halfs per uint2)
#define WMAX 64        // ELL width; P(Poisson(12.5) >= 64) ~ 1e-23

// ---------------- scratch (device globals, allocation-free) ----------------
// g_meta: [0:NN)=cnt0, [NN:2NN)=cnt1, [2NN:3NN)=degf (float bits) — one memset
__device__ int   g_meta[3 * NN];
__device__ float g_dis[NN];
__device__ int2  g_ell0[(size_t)NN * WMAX];   // edge graph: {col*16, w_raw}
__device__ int2  g_ell1[(size_t)NN * WMAX];   // nb graph: {col*16, w}
__device__ uint2 g_xh[NH2];      // x fp16
__device__ uint2 g_xs[NH2];      // dis*x fp16 (gather operand for L1)
__device__ uint2 g_lxh[NH2];     // Lx fp16 (row terms)
__device__ uint2 g_lxs[NH2];     // dis*Lx fp16 (gather operand for L2)
__device__ uint2 g_outh[NH2];    // out fp16
__device__ uint4 g_o12[(size_t)NN * 16];  // interleaved {out 8B, out[shuf] 8B} per lane
__device__ uint4 g_b12[(size_t)NN * 16];  // interleaved {N(out) 8B, N(out_shuf) 8B} per lane

// ---------------- helpers ----------------
__device__ __forceinline__ void fma4(float* acc, uint2 v, float w) {
    __half2 h0 = *reinterpret_cast<__half2*>(&v.x);
    __half2 h1 = *reinterpret_cast<__half2*>(&v.y);
    float2 f0 = __half22float2(h0);
    float2 f1 = __half22float2(h1);
    acc[0] += w * f0.x;
    acc[1] += w * f0.y;
    acc[2] += w * f1.x;
    acc[3] += w * f1.y;
}

__device__ __forceinline__ float4 unpack4(uint2 v) {
    __half2 h0 = *reinterpret_cast<__half2*>(&v.x);
    __half2 h1 = *reinterpret_cast<__half2*>(&v.y);
    float2 f0 = __half22float2(h0);
    float2 f1 = __half22float2(h1);
    return make_float4(f0.x, f0.y, f1.x, f1.y);
}

__device__ __forceinline__ uint2 pack4(float a, float b, float c, float d) {
    uint2 u;
    __half2 h0 = __floats2half2_rn(a, b);
    __half2 h1 = __floats2half2_rn(c, d);
    u.x = *reinterpret_cast<unsigned*>(&h0);
    u.y = *reinterpret_cast<unsigned*>(&h1);
    return u;
}

// ---------------- build: fused ELL append (both graphs) + fp16 x ----------------
__global__ void append_all_kernel(const int* __restrict__ er, const int* __restrict__ ec,
                                  const float* __restrict__ ew,
                                  const int* __restrict__ nr, const int* __restrict__ nc,
                                  const float* __restrict__ nw,
                                  const float* __restrict__ x) {
    int i = blockIdx.x * blockDim.x + threadIdx.x;
    if (i < EE) {
        int r = er[i];
        float w = ew[i];
        atomicAdd((float*)&g_meta[2 * NN + r], w);
        int p = atomicAdd(&g_meta[r], 1);
        g_ell0[(size_t)r * WMAX + p] = make_int2(ec[i] * 16, __float_as_int(w));
    } else if (i < 2 * EE) {
        int k = i - EE;
        int r = nr[k];
        int p = atomicAdd(&g_meta[NN + r], 1);
        g_ell1[(size_t)r * WMAX + p] = make_int2(nc[k] * 16, __float_as_int(nw[k]));
    } else if (i < 2 * EE + NH2) {
        int k = i - 2 * EE;
        float4 v = *(const float4*)(x + (size_t)k * 4);
        g_xh[k] = pack4(v.x, v.y, v.z, v.w);
    }
}

// dis[r] = rsqrt(degf[r]) (once per row); xs = dis * x (HMUL2)
__global__ void dis_scale_kernel() {
    int t = blockIdx.x * blockDim.x + threadIdx.x;
    int r = t >> 4;
    if (r >= NN) return;
    unsigned wl = threadIdx.x & 31;
    float dr_l = 0.f;
    if ((wl & 15) == 0) {
        float d = __int_as_float(g_meta[2 * NN + r]);
        dr_l = (d > 0.f) ? rsqrtf(d) : 0.f;
    }
    float dr = __shfl_sync(0xffffffffu, dr_l, wl & 16);
    if ((wl & 15) == 0) g_dis[r] = dr;
    unsigned idx = (unsigned)r * 16u + (t & 15);
    uint2 v = g_xh[idx];
    __half2 dh = __float2half2_rn(dr);
    __half2 a = __hmul2(*reinterpret_cast<__half2*>(&v.x), dh);
    __half2 b = __hmul2(*reinterpret_cast<__half2*>(&v.y), dh);
    uint2 o;
    o.x = *reinterpret_cast<unsigned*>(&a);
    o.y = *reinterpret_cast<unsigned*>(&b);
    g_xs[idx] = o;
}

// ---------------- SPMM kernels: 16 lanes per row, 4 features per lane ----------------

// Lx = x - dis[r] * sum w*xs[col]; writes lxh + lxs fp16
__global__ void spmm_L1_kernel() {
    int t = blockIdx.x * blockDim.x + threadIdx.x;
    int r = t >> 4;
    if (r >= NN) return;
    unsigned lane = t & 15;
    int deg = g_meta[r];
    float dr = g_dis[r];
    const size_t base = (size_t)r * WMAX;
    float acc[4] = {0.f, 0.f, 0.f, 0.f};
    int j = 0;
    for (; j + 2 <= deg; j += 2) {
        int4 ee = *(const int4*)&g_ell0[base + j];   // two edges in one LDG.128
        uint2 v0 = g_xs[(unsigned)ee.x + lane];
        uint2 v1 = g_xs[(unsigned)ee.z + lane];
        fma4(acc, v0, __int_as_float(ee.y));
        fma4(acc, v1, __int_as_float(ee.w));
    }
    if (j < deg) {
        int2 e0 = g_ell0[base + j];
        uint2 v0 = g_xs[(unsigned)e0.x + lane];
        fma4(acc, v0, __int_as_float(e0.y));
    }
    unsigned idx = (unsigned)r * 16u + lane;
    float4 xv = unpack4(g_xh[idx]);
    float l0 = xv.x - dr * acc[0];
    float l1 = xv.y - dr * acc[1];
    float l2 = xv.z - dr * acc[2];
    float l3 = xv.w - dr * acc[3];
    g_lxh[idx] = pack4(l0, l1, l2, l3);
    g_lxs[idx] = pack4(dr * l0, dr * l1, dr * l2, dr * l3);
}

// out = c0*x + c1*Lx + c2*(Lx - dis[r]*sum w*lxs[col]); writes out fp32 + outh fp16
__global__ void spmm_L2_kernel(const float* __restrict__ temp,
                               float* __restrict__ out) {
    int t = blockIdx.x * blockDim.x + threadIdx.x;
    int r = t >> 4;
    if (r >= NN) return;
    unsigned lane = t & 15;
    int deg = g_meta[r];
    float dr = g_dis[r];
    const size_t base = (size_t)r * WMAX;
    float acc[4] = {0.f, 0.f, 0.f, 0.f};
    int j = 0;
    for (; j + 2 <= deg; j += 2) {
        int4 ee = *(const int4*)&g_ell0[base + j];
        uint2 v0 = g_lxs[(unsigned)ee.x + lane];
        uint2 v1 = g_lxs[(unsigned)ee.z + lane];
        fma4(acc, v0, __int_as_float(ee.y));
        fma4(acc, v1, __int_as_float(ee.w));
    }
    if (j < deg) {
        int2 e0 = g_ell0[base + j];
        uint2 v0 = g_lxs[(unsigned)e0.x + lane];
        fma4(acc, v0, __int_as_float(e0.y));
    }
    float t0 = fmaxf(__ldg(temp + 0), 0.f);
    float t1 = fmaxf(__ldg(temp + 1), 0.f);
    float t2 = fmaxf(__ldg(temp + 2), 0.f);
    float c0 = t0;
    float c1 = t1 - t0;
    float c2 = (t0 + t2 - 2.f * t1) * 0.25f;
    unsigned idx = (unsigned)r * 16u + lane;
    float4 xv = unpack4(g_xh[idx]);
    float4 lv = unpack4(g_lxh[idx]);
    float o0 = c0 * xv.x + c1 * lv.x + c2 * (lv.x - dr * acc[0]);
    float o1 = c0 * xv.y + c1 * lv.y + c2 * (lv.y - dr * acc[1]);
    float o2 = c0 * xv.z + c1 * lv.z + c2 * (lv.z - dr * acc[2]);
    float o3 = c0 * xv.w + c1 * lv.w + c2 * (lv.w - dr * acc[3]);
    *(float4*)(out + (size_t)r * DD + lane * 4u) = make_float4(o0, o1, o2, o3);
    g_outh[idx] = pack4(o0, o1, o2, o3);
}

// interleave: o12[r] = {outh[r], outh[shuf[r]]} per lane
__global__ void interleave_kernel(const int* __restrict__ shuf) {
    int t = blockIdx.x * blockDim.x + threadIdx.x;
    int r = t >> 4;
    if (r >= NN) return;
    unsigned lane = t & 15;
    int s = __ldg(shuf + r);
    uint2 a = g_outh[(unsigned)r * 16u + lane];
    uint2 b = g_outh[(unsigned)s * 16u + lane];
    g_o12[(unsigned)r * 16u + lane] = make_uint4(a.x, a.y, b.x, b.y);
}

// dual hop 1: one uint4 gather per edge-lane serves both pos & neg accumulators
__global__ void spmm_N1_kernel() {
    int t = blockIdx.x * blockDim.x + threadIdx.x;
    int r = t >> 4;
    if (r >= NN) return;
    unsigned lane = t & 15;
    int deg = g_meta[NN + r];
    const size_t base = (size_t)r * WMAX;
    float ap[4] = {0.f, 0.f, 0.f, 0.f};
    float an[4] = {0.f, 0.f, 0.f, 0.f};
    int j = 0;
    for (; j + 2 <= deg; j += 2) {
        int4 ee = *(const int4*)&g_ell1[base + j];   // {c0,w0,c1,w1}
        uint4 v0 = g_o12[(unsigned)ee.x + lane];
        uint4 v1 = g_o12[(unsigned)ee.z + lane];
        float w0 = __int_as_float(ee.y), w1 = __int_as_float(ee.w);
        fma4(ap, make_uint2(v0.x, v0.y), w0);
        fma4(an, make_uint2(v0.z, v0.w), w0);
        fma4(ap, make_uint2(v1.x, v1.y), w1);
        fma4(an, make_uint2(v1.z, v1.w), w1);
    }
    if (j < deg) {
        int2 e0 = g_ell1[base + j];
        float w0 = __int_as_float(e0.y);
        uint4 v0 = g_o12[(unsigned)e0.x + lane];
        fma4(ap, make_uint2(v0.x, v0.y), w0);
        fma4(an, make_uint2(v0.z, v0.w), w0);
    }
    uint2 up = pack4(ap[0], ap[1], ap[2], ap[3]);
    uint2 un = pack4(an[0], an[1], an[2], an[3]);
    g_b12[(unsigned)r * 16u + lane] = make_uint4(up.x, up.y, un.x, un.y);
}

// dual hop 2: one uint4 gather per edge-lane fetches both pos & neg operands
__global__ void spmm_N2_kernel(float* __restrict__ zp, float* __restrict__ zn) {
    int t = blockIdx.x * blockDim.x + threadIdx.x;
    int r = t >> 4;
    if (r >= NN) return;
    unsigned lane = t & 15;
    int deg = g_meta[NN + r];
    const size_t base = (size_t)r * WMAX;
    float ap[4] = {0.f, 0.f, 0.f, 0.f};
    float an[4] = {0.f, 0.f, 0.f, 0.f};
    int j = 0;
    for (; j + 2 <= deg; j += 2) {
        int4 ee = *(const int4*)&g_ell1[base + j];
        uint4 v0 = g_b12[(unsigned)ee.x + lane];
        uint4 v1 = g_b12[(unsigned)ee.z + lane];
        float w0 = __int_as_float(ee.y), w1 = __int_as_float(ee.w);
        fma4(ap, make_uint2(v0.x, v0.y), w0);
        fma4(an, make_uint2(v0.z, v0.w), w0);
        fma4(ap, make_uint2(v1.x, v1.y), w1);
        fma4(an, make_uint2(v1.z, v1.w), w1);
    }
    if (j < deg) {
        int2 e0 = g_ell1[base + j];
        float w0 = __int_as_float(e0.y);
        uint4 v0 = g_b12[(unsigned)e0.x + lane];
        fma4(ap, make_uint2(v0.x, v0.y), w0);
        fma4(an, make_uint2(v0.z, v0.w), w0);
    }
    *(float4*)(zp + (size_t)r * DD + lane * 4u) = make_float4(ap[0], ap[1], ap[2], ap[3]);
    *(float4*)(zn + (size_t)r * DD + lane * 4u) = make_float4(an[0], an[1], an[2], an[3]);
}

extern "C" void kernel_launch(void* const* d_in, const int* in_sizes, int n_in,
                              void* d_out, int out_size) {
    const float* x    = (const float*)d_in[0];
    const int*   shuf = (const int*)  d_in[1];
    const int*   ei   = (const int*)  d_in[2];
    const float* ew   = (const float*)d_in[3];
    const int*   ni   = (const int*)  d_in[4];
    const float* nw   = (const float*)d_in[5];
    const float* temp = (const float*)d_in[6];
    float* out = (float*)d_out;   // [out | z_pos | z_neg]

    const int* erow = ei;
    const int* ecol = ei + EE;
    const int* nrow = ni;
    const int* ncol = ni + EE;

    void* p_meta;
    cudaGetSymbolAddress(&p_meta, g_meta);

    const int TB = 256;
    const int blkALL = (2 * EE + NH2 + TB - 1) / TB;
    const int blkR16 = (NN * 16 + TB - 1) / TB;

    // ---- build: one memset, fused append (both graphs) + fp16 x ----
    cudaMemsetAsync(p_meta, 0, 3 * NN * sizeof(int), 0);
    append_all_kernel<<<blkALL, TB>>>(erow, ecol, ew, nrow, ncol, nw, x);
    dis_scale_kernel<<<blkR16, TB>>>();

    // ---- spectral polynomial ----
    spmm_L1_kernel<<<blkR16, TB>>>();
    spmm_L2_kernel<<<blkR16, TB>>>(temp, out);

    // ---- z_pos / z_neg ----
    interleave_kernel<<<blkR16, TB>>>(shuf);
    spmm_N1_kernel<<<blkR16, TB>>>();
    spmm_N2_kernel<<<blkR16, TB>>>(out + (size_t)ND, out + 2 * (size_t)ND);
}